// round 7
// baseline (speedup 1.0000x reference)
#include <cuda_runtime.h>

#define N_UNITS 8
#define M_ATOMS 1024
#define NPTS (N_UNITS * M_ATOMS)      // 8192
#define N_PAIRS 28
#define LOG2E 1.4426950408889634f
#define ALPHA 1.0f
#define LAMBDA1 0.5f

// ---------------- device scratch (allocation-free) ----------------
// g_u[idx] = (2*log2e*x, 2*log2e*y, 2*log2e*z, h) per transformed point
// g_vp: transposed j-side: per unit, per j-pair jj:
//   [jj][0]={x0,x1} [jj][1]={y0,y1} [jj][2]={z0,z1} [jj][3]={h0,h1}
__device__ float4 g_u[NPTS];
__device__ __align__(16) float g_vp[N_UNITS][M_ATOMS / 2][4][2];
__device__ float g_acc;           // zero-init; reset by last CTA each run
__device__ unsigned int g_count;  // zero-init; reset by last CTA each run

// pair (a,b) lookup, a < b
__constant__ unsigned char c_pa[N_PAIRS] =
    {0,0,0,0,0,0,0,1,1,1,1,1,1,2,2,2,2,2,3,3,3,3,4,4,4,5,5,6};
__constant__ unsigned char c_pb[N_PAIRS] =
    {1,2,3,4,5,6,7,2,3,4,5,6,7,3,4,5,6,7,4,5,6,7,5,6,7,6,7,7};

// ---------------- helpers ----------------
__device__ __forceinline__ unsigned long long pack2(float a, float b) {
    unsigned long long r;
    asm("mov.b64 %0, {%1, %2};" : "=l"(r) : "f"(a), "f"(b));
    return r;
}
__device__ __forceinline__ void unpack2(unsigned long long p, float& lo, float& hi) {
    asm("mov.b64 {%0, %1}, %2;" : "=f"(lo), "=f"(hi) : "l"(p));
}
__device__ __forceinline__ unsigned long long fma2(unsigned long long a,
                                                   unsigned long long b,
                                                   unsigned long long c) {
    unsigned long long d;
    asm("fma.rn.f32x2 %0, %1, %2, %3;" : "=l"(d) : "l"(a), "l"(b), "l"(c));
    return d;
}
__device__ __forceinline__ unsigned long long add2(unsigned long long a,
                                                   unsigned long long b) {
    unsigned long long d;
    asm("add.rn.f32x2 %0, %1, %2;" : "=l"(d) : "l"(a), "l"(b));
    return d;
}
// pack two f32 into f16x2 (order irrelevant: both halves are summed)
__device__ __forceinline__ unsigned int cvt_f16x2(float a, float b) {
    unsigned int r;
    asm("cvt.rn.f16x2.f32 %0, %1, %2;" : "=r"(r) : "f"(a), "f"(b));
    return r;
}
// 2 exps in ONE MUFU instruction
__device__ __forceinline__ unsigned int ex2_f16x2(unsigned int x) {
    unsigned int y;
    asm("ex2.approx.f16x2 %0, %1;" : "=r"(y) : "r"(x));
    return y;
}
// widen both halves back to f32 for exact accumulation
__device__ __forceinline__ void f16x2_to_f32(unsigned int p, float& a, float& b) {
    asm("{ .reg .f16 lo, hi;\n"
        "  mov.b32 {lo, hi}, %2;\n"
        "  cvt.f32.f16 %0, lo;\n"
        "  cvt.f32.f16 %1, hi; }"
        : "=f"(a), "=f"(b) : "r"(p));
}

// ---------------- kernel 1: prep ----------------
__global__ void __launch_bounds__(256) k_prep(const float* __restrict__ pos,
                                              const float* __restrict__ eul,
                                              const float* __restrict__ coord)
{
    __shared__ float sR[12];
    int bid = blockIdx.x;
    int n = bid >> 2;
    int m = ((bid & 3) << 8) + threadIdx.x;

    if (threadIdx.x == 0) {
        float phi   = eul[3 * n + 0];
        float theta = eul[3 * n + 1];
        float psi   = eul[3 * n + 2];
        float sp, cp, st, ct, ss, cs;
        sincosf(phi,   &sp, &cp);
        sincosf(theta, &st, &ct);
        sincosf(psi,   &ss, &cs);
        sR[0] = cs * ct;
        sR[1] = cs * st * sp - ss * cp;
        sR[2] = cs * st * cp + ss * sp;
        sR[3] = ss * ct;
        sR[4] = ss * st * sp + cs * cp;
        sR[5] = ss * st * cp - cs * sp;
        sR[6] = -st;
        sR[7] = ct * sp;
        sR[8] = ct * cp;
        sR[9]  = pos[3 * n + 0];
        sR[10] = pos[3 * n + 1];
        sR[11] = pos[3 * n + 2];
    }
    __syncthreads();

    float cx = coord[3 * m + 0];
    float cy = coord[3 * m + 1];
    float cz = coord[3 * m + 2];

    float tx = fmaf(sR[0], cx, fmaf(sR[1], cy, fmaf(sR[2], cz, sR[9])));
    float ty = fmaf(sR[3], cx, fmaf(sR[4], cy, fmaf(sR[5], cz, sR[10])));
    float tz = fmaf(sR[6], cx, fmaf(sR[7], cy, fmaf(sR[8], cz, sR[11])));

    float sq = fmaf(tx, tx, fmaf(ty, ty, tz * tz));
    float h  = LOG2E * (0.5f - sq);

    int idx = n * M_ATOMS + m;
    g_u[idx] = make_float4(2.0f * LOG2E * tx,
                           2.0f * LOG2E * ty,
                           2.0f * LOG2E * tz, h);

    int jj = m >> 1, half = m & 1;
    g_vp[n][jj][0][half] = tx;
    g_vp[n][jj][1][half] = ty;
    g_vp[n][jj][2][half] = tz;
    g_vp[n][jj][3][half] = h;

    float t = sq;
    #pragma unroll
    for (int o = 16; o > 0; o >>= 1)
        t += __shfl_down_sync(0xFFFFFFFFu, t, o);
    __shared__ float ws[8];
    int lane = threadIdx.x & 31, wid = threadIdx.x >> 5;
    if (lane == 0) ws[wid] = t;
    __syncthreads();
    if (threadIdx.x == 0) {
        float s = 0.0f;
        #pragma unroll
        for (int w = 0; w < 8; w++) s += ws[w];
        atomicAdd(&g_acc, s * (1.0f / (float)N_UNITS));
    }

    if (bid == 0 && threadIdx.x == 32) {
        float sx = 0.0f, sy = 0.0f, sz = 0.0f;
        #pragma unroll
        for (int k = 0; k < N_UNITS; k++) {
            sx += pos[3 * k + 0];
            sy += pos[3 * k + 1];
            sz += pos[3 * k + 2];
        }
        atomicAdd(&g_acc, ALPHA * (sx * sx + sy * sy + sz * sz));
    }
}

// ---------------- kernel 2: pairs ----------------
// 28 pairs x 4 i-tiles(256) x 32 j-tiles(32) = 3584 CTAs, 128 threads.
// Each thread: 2 i-points x 32 j-points = 64 pairs; j packed 2-wide.
// exp path: s computed in f32x2, converted to f16x2, ONE ex2.approx.f16x2
// per 2 pairs (halves MUFU instruction count = the measured roofline),
// widened back to f32 for accumulation.
#define TPB 128
#define I_PER_THREAD 2
#define ITILE (TPB * I_PER_THREAD)   // 256
#define JTILE 32
#define NJJ (JTILE / 2)              // 16 packed iterations
#define PAIR_CTAS (N_PAIRS * (M_ATOMS / ITILE) * (M_ATOMS / JTILE))  // 3584

__global__ void __launch_bounds__(TPB, 12) k_pairs(float* __restrict__ out)
{
    int bid     = blockIdx.x;
    int pairIdx = bid >> 7;          // 128 tiles per pair (4 i x 32 j)
    int rem     = bid & 127;
    int iTile   = rem >> 5;          // 0..3
    int jTile   = rem & 31;          // 0..31

    int a = c_pa[pairIdx];
    int b = c_pb[pairIdx];

    int ibase = a * M_ATOMS + iTile * ITILE + threadIdx.x * I_PER_THREAD;
    int jj0   = jTile * NJJ;

    float4 u0 = __ldg(&g_u[ibase + 0]);
    float4 u1 = __ldg(&g_u[ibase + 1]);
    unsigned long long u0x = pack2(u0.x, u0.x), u0y = pack2(u0.y, u0.y),
                       u0z = pack2(u0.z, u0.z), u0w = pack2(u0.w, u0.w);
    unsigned long long u1x = pack2(u1.x, u1.x), u1y = pack2(u1.y, u1.y),
                       u1z = pack2(u1.z, u1.z), u1w = pack2(u1.w, u1.w);

    float acc0 = 0.f, acc1 = 0.f, acc2 = 0.f, acc3 = 0.f;

    const ulonglong2* __restrict__ vp = (const ulonglong2*)&g_vp[b][jj0][0][0];

    #pragma unroll 4
    for (int q = 0; q < NJJ; q++) {
        ulonglong2 P0 = vp[2 * q + 0];   // {xx, yy}
        ulonglong2 P1 = vp[2 * q + 1];   // {zz, ww}

        unsigned long long s0 =
            fma2(u0x, P0.x, fma2(u0y, P0.y, fma2(u0z, P1.x, add2(u0w, P1.y))));
        unsigned long long s1 =
            fma2(u1x, P0.x, fma2(u1y, P0.y, fma2(u1z, P1.x, add2(u1w, P1.y))));

        float lo0, hi0, lo1, hi1;
        unpack2(s0, lo0, hi0);
        unpack2(s1, lo1, hi1);

        unsigned int e0 = ex2_f16x2(cvt_f16x2(lo0, hi0));  // 2 exps, 1 MUFU op
        unsigned int e1 = ex2_f16x2(cvt_f16x2(lo1, hi1));

        float f0a, f0b, f1a, f1b;
        f16x2_to_f32(e0, f0a, f0b);
        f16x2_to_f32(e1, f1a, f1b);
        acc0 += f0a;
        acc1 += f0b;
        acc2 += f1a;
        acc3 += f1b;
    }

    float t = (acc0 + acc1) + (acc2 + acc3);
    #pragma unroll
    for (int o = 16; o > 0; o >>= 1)
        t += __shfl_down_sync(0xFFFFFFFFu, t, o);

    __shared__ float ws[TPB / 32];
    int lane = threadIdx.x & 31, wid = threadIdx.x >> 5;
    if (lane == 0) ws[wid] = t;
    __syncthreads();

    if (threadIdx.x == 0) {
        float s = 0.0f;
        #pragma unroll
        for (int w = 0; w < TPB / 32; w++) s += ws[w];
        atomicAdd(&g_acc, LAMBDA1 * s);
        __threadfence();
        unsigned int nDone = atomicAdd(&g_count, 1u);
        if (nDone == PAIR_CTAS - 1) {
            float total = atomicExch(&g_acc, 0.0f);
            out[0] = total;
            atomicExch(&g_count, 0u);
        }
    }
}

extern "C" void kernel_launch(void* const* d_in, const int* in_sizes, int n_in,
                              void* d_out, int out_size)
{
    const float* positions    = (const float*)d_in[0];
    const float* euler_angles = (const float*)d_in[1];
    const float* coordinates  = (const float*)d_in[2];
    float* out = (float*)d_out;
    (void)in_sizes; (void)n_in; (void)out_size;

    k_prep<<<NPTS / 256, 256>>>(positions, euler_angles, coordinates);
    k_pairs<<<PAIR_CTAS, TPB>>>(out);
}

// round 8
// speedup vs baseline: 1.0823x; 1.0823x over previous
#include <cuda_runtime.h>

#define N_UNITS 8
#define M_ATOMS 1024
#define NPTS (N_UNITS * M_ATOMS)      // 8192
#define N_PAIRS 28
#define LOG2E 1.4426950408889634f
#define ALPHA 1.0f
#define LAMBDA1 0.5f

// ---------------- device scratch (allocation-free) ----------------
__device__ float4 g_u[NPTS];
__device__ __align__(16) float g_vp[N_UNITS][M_ATOMS / 2][4][2];
__device__ float g_acc;           // zero-init; reset by last CTA each run
__device__ unsigned int g_count;  // zero-init; reset by last CTA each run

__constant__ unsigned char c_pa[N_PAIRS] =
    {0,0,0,0,0,0,0,1,1,1,1,1,1,2,2,2,2,2,3,3,3,3,4,4,4,5,5,6};
__constant__ unsigned char c_pb[N_PAIRS] =
    {1,2,3,4,5,6,7,2,3,4,5,6,7,3,4,5,6,7,4,5,6,7,5,6,7,6,7,7};

// ---------------- helpers ----------------
__device__ __forceinline__ float ex2_approx(float x) {
    float y;
    asm("ex2.approx.ftz.f32 %0, %1;" : "=f"(y) : "f"(x));
    return y;
}
__device__ __forceinline__ unsigned long long pack2(float a, float b) {
    unsigned long long r;
    asm("mov.b64 %0, {%1, %2};" : "=l"(r) : "f"(a), "f"(b));
    return r;
}
__device__ __forceinline__ void unpack2(unsigned long long p, float& lo, float& hi) {
    asm("mov.b64 {%0, %1}, %2;" : "=f"(lo), "=f"(hi) : "l"(p));
}
__device__ __forceinline__ unsigned long long fma2(unsigned long long a,
                                                   unsigned long long b,
                                                   unsigned long long c) {
    unsigned long long d;
    asm("fma.rn.f32x2 %0, %1, %2, %3;" : "=l"(d) : "l"(a), "l"(b), "l"(c));
    return d;
}
__device__ __forceinline__ unsigned long long add2(unsigned long long a,
                                                   unsigned long long b) {
    unsigned long long d;
    asm("add.rn.f32x2 %0, %1, %2;" : "=l"(d) : "l"(a), "l"(b));
    return d;
}

// Taylor coefficients for 2^f, f in [-0.5, 0.5]
#define EXP2_C1 0.6931471805599453f
#define EXP2_C2 0.2402265069591007f
#define EXP2_C3 0.0555041086648216f
#define EXP2_C4 0.0096181291076285f
#define MAGIC   12582912.0f            // 1.5 * 2^23
#define MAGIC_BITS 0x4B400000u
#define TBITS_MIN  (MAGIC_BITS - 125u) // clamp n >= -125

// ---------------- kernel 1: prep ----------------
__global__ void __launch_bounds__(256) k_prep(const float* __restrict__ pos,
                                              const float* __restrict__ eul,
                                              const float* __restrict__ coord)
{
    __shared__ float sR[12];
    int bid = blockIdx.x;
    int n = bid >> 2;
    int m = ((bid & 3) << 8) + threadIdx.x;

    if (threadIdx.x == 0) {
        float phi   = eul[3 * n + 0];
        float theta = eul[3 * n + 1];
        float psi   = eul[3 * n + 2];
        float sp, cp, st, ct, ss, cs;
        sincosf(phi,   &sp, &cp);
        sincosf(theta, &st, &ct);
        sincosf(psi,   &ss, &cs);
        sR[0] = cs * ct;
        sR[1] = cs * st * sp - ss * cp;
        sR[2] = cs * st * cp + ss * sp;
        sR[3] = ss * ct;
        sR[4] = ss * st * sp + cs * cp;
        sR[5] = ss * st * cp - cs * sp;
        sR[6] = -st;
        sR[7] = ct * sp;
        sR[8] = ct * cp;
        sR[9]  = pos[3 * n + 0];
        sR[10] = pos[3 * n + 1];
        sR[11] = pos[3 * n + 2];
    }
    __syncthreads();

    float cx = coord[3 * m + 0];
    float cy = coord[3 * m + 1];
    float cz = coord[3 * m + 2];

    float tx = fmaf(sR[0], cx, fmaf(sR[1], cy, fmaf(sR[2], cz, sR[9])));
    float ty = fmaf(sR[3], cx, fmaf(sR[4], cy, fmaf(sR[5], cz, sR[10])));
    float tz = fmaf(sR[6], cx, fmaf(sR[7], cy, fmaf(sR[8], cz, sR[11])));

    float sq = fmaf(tx, tx, fmaf(ty, ty, tz * tz));
    float h  = LOG2E * (0.5f - sq);

    int idx = n * M_ATOMS + m;
    g_u[idx] = make_float4(2.0f * LOG2E * tx,
                           2.0f * LOG2E * ty,
                           2.0f * LOG2E * tz, h);

    int jj = m >> 1, half = m & 1;
    g_vp[n][jj][0][half] = tx;
    g_vp[n][jj][1][half] = ty;
    g_vp[n][jj][2][half] = tz;
    g_vp[n][jj][3][half] = h;

    float t = sq;
    #pragma unroll
    for (int o = 16; o > 0; o >>= 1)
        t += __shfl_down_sync(0xFFFFFFFFu, t, o);
    __shared__ float ws[8];
    int lane = threadIdx.x & 31, wid = threadIdx.x >> 5;
    if (lane == 0) ws[wid] = t;
    __syncthreads();
    if (threadIdx.x == 0) {
        float s = 0.0f;
        #pragma unroll
        for (int w = 0; w < 8; w++) s += ws[w];
        atomicAdd(&g_acc, s * (1.0f / (float)N_UNITS));
    }

    if (bid == 0 && threadIdx.x == 32) {
        float sx = 0.0f, sy = 0.0f, sz = 0.0f;
        #pragma unroll
        for (int k = 0; k < N_UNITS; k++) {
            sx += pos[3 * k + 0];
            sy += pos[3 * k + 1];
            sz += pos[3 * k + 2];
        }
        atomicAdd(&g_acc, ALPHA * (sx * sx + sy * sy + sz * sz));
    }
}

// ---------------- kernel 2: pairs ----------------
// 28 pairs x 4 i-tiles(256) x 16 j-tiles(64) = 1792 CTAs, 128 threads.
// Each thread: 2 i-points x 64 j-points; j packed 2-wide (f32x2).
// Hybrid exp: i0's exps on MUFU (ex2.approx.f32), i1's exps on the FMA pipe
// via packed polynomial exp2 — the two pipes run concurrently.
#define TPB 128
#define I_PER_THREAD 2
#define ITILE (TPB * I_PER_THREAD)   // 256
#define JTILE 64
#define NJJ (JTILE / 2)              // 32 packed iterations
#define PAIR_CTAS (N_PAIRS * (M_ATOMS / ITILE) * (M_ATOMS / JTILE))  // 1792

__global__ void __launch_bounds__(TPB) k_pairs(float* __restrict__ out)
{
    int bid     = blockIdx.x;
    int pairIdx = bid >> 6;
    int rem     = bid & 63;
    int iTile   = rem >> 4;
    int jTile   = rem & 15;

    int a = c_pa[pairIdx];
    int b = c_pb[pairIdx];

    int ibase = a * M_ATOMS + iTile * ITILE + threadIdx.x * I_PER_THREAD;
    int jj0   = jTile * NJJ;

    float4 u0 = __ldg(&g_u[ibase + 0]);
    float4 u1 = __ldg(&g_u[ibase + 1]);
    unsigned long long u0x = pack2(u0.x, u0.x), u0y = pack2(u0.y, u0.y),
                       u0z = pack2(u0.z, u0.z), u0w = pack2(u0.w, u0.w);
    unsigned long long u1x = pack2(u1.x, u1.x), u1y = pack2(u1.y, u1.y),
                       u1z = pack2(u1.z, u1.z), u1w = pack2(u1.w, u1.w);

    // packed constants for the polynomial path
    const unsigned long long magic2  = pack2(MAGIC, MAGIC);
    const unsigned long long nmagic2 = pack2(-MAGIC, -MAGIC);
    const unsigned long long none2   = pack2(-1.0f, -1.0f);
    const unsigned long long k1_2    = pack2(EXP2_C1, EXP2_C1);
    const unsigned long long k2_2    = pack2(EXP2_C2, EXP2_C2);
    const unsigned long long k3_2    = pack2(EXP2_C3, EXP2_C3);
    const unsigned long long k4_2    = pack2(EXP2_C4, EXP2_C4);
    const unsigned long long one2    = pack2(1.0f, 1.0f);

    float accM0 = 0.f, accM1 = 0.f;                 // MUFU path accumulators
    unsigned long long accP = pack2(0.0f, 0.0f);    // poly path accumulator

    const ulonglong2* __restrict__ vp = (const ulonglong2*)&g_vp[b][jj0][0][0];

    #pragma unroll 4
    for (int q = 0; q < NJJ; q++) {
        ulonglong2 P0 = vp[2 * q + 0];   // {xx, yy}
        ulonglong2 P1 = vp[2 * q + 1];   // {zz, ww}

        // ---- i0: MUFU path ----
        unsigned long long s0 =
            fma2(u0x, P0.x, fma2(u0y, P0.y, fma2(u0z, P1.x, add2(u0w, P1.y))));
        float lo0, hi0;
        unpack2(s0, lo0, hi0);
        accM0 += ex2_approx(lo0);
        accM1 += ex2_approx(hi0);

        // ---- i1: polynomial path (FMA pipe) ----
        unsigned long long s1 =
            fma2(u1x, P0.x, fma2(u1y, P0.y, fma2(u1z, P1.x, add2(u1w, P1.y))));

        unsigned long long t2 = add2(s1, magic2);       // n captured in mantissa
        unsigned long long r2 = add2(t2, nmagic2);      // r = round(s)
        unsigned long long f2 = fma2(r2, none2, s1);    // f = s - r, [-0.5,0.5]

        unsigned long long p2 = fma2(f2, k4_2, k3_2);
        p2 = fma2(f2, p2, k2_2);
        p2 = fma2(f2, p2, k1_2);
        p2 = fma2(f2, p2, one2);                        // p = 2^f

        float tlo, thi, plo, phi_;
        unpack2(t2, tlo, thi);
        unpack2(p2, plo, phi_);

        unsigned int tb0 = __float_as_uint(tlo);
        unsigned int tb1 = __float_as_uint(thi);
        tb0 = (tb0 < TBITS_MIN) ? TBITS_MIN : tb0;      // clamp n >= -125
        tb1 = (tb1 < TBITS_MIN) ? TBITS_MIN : tb1;
        float pen0 = __uint_as_float(__float_as_uint(plo)  + (tb0 << 23));
        float pen1 = __uint_as_float(__float_as_uint(phi_) + (tb1 << 23));

        accP = add2(accP, pack2(pen0, pen1));
    }

    float pA, pB;
    unpack2(accP, pA, pB);
    float t = (accM0 + accM1) + (pA + pB);
    #pragma unroll
    for (int o = 16; o > 0; o >>= 1)
        t += __shfl_down_sync(0xFFFFFFFFu, t, o);

    __shared__ float ws[TPB / 32];
    int lane = threadIdx.x & 31, wid = threadIdx.x >> 5;
    if (lane == 0) ws[wid] = t;
    __syncthreads();

    if (threadIdx.x == 0) {
        float s = 0.0f;
        #pragma unroll
        for (int w = 0; w < TPB / 32; w++) s += ws[w];
        atomicAdd(&g_acc, LAMBDA1 * s);
        __threadfence();
        unsigned int nDone = atomicAdd(&g_count, 1u);
        if (nDone == PAIR_CTAS - 1) {
            float total = atomicExch(&g_acc, 0.0f);
            out[0] = total;
            atomicExch(&g_count, 0u);
        }
    }
}

extern "C" void kernel_launch(void* const* d_in, const int* in_sizes, int n_in,
                              void* d_out, int out_size)
{
    const float* positions    = (const float*)d_in[0];
    const float* euler_angles = (const float*)d_in[1];
    const float* coordinates  = (const float*)d_in[2];
    float* out = (float*)d_out;
    (void)in_sizes; (void)n_in; (void)out_size;

    k_prep<<<NPTS / 256, 256>>>(positions, euler_angles, coordinates);
    k_pairs<<<PAIR_CTAS, TPB>>>(out);
}

// round 11
// speedup vs baseline: 1.5302x; 1.4138x over previous
#include <cuda_runtime.h>

#define N_UNITS 8
#define M_ATOMS 1024
#define N_PAIRS 28
#define LOG2E 1.4426950408889634f
#define ALPHA 1.0f
#define LAMBDA1 0.5f

// fused kernel tiling
#define TPB 128
#define I_PER_THREAD 2
#define ITILE (TPB * I_PER_THREAD)     // 256
#define JTILE 128
#define NJJ (JTILE / 2)                // 64 packed iterations
#define TILES_PER_PAIR ((M_ATOMS / ITILE) * (M_ATOMS / JTILE))  // 4*8 = 32
#define PAIR_CTAS (N_PAIRS * TILES_PER_PAIR)                    // 896

// ---------------- device scratch (allocation-free, stateless) ----------------
// g_part[bid] is fully overwritten by every run -> no reset protocol needed.
__device__ float g_part[PAIR_CTAS];

__constant__ unsigned char c_pa[N_PAIRS] =
    {0,0,0,0,0,0,0,1,1,1,1,1,1,2,2,2,2,2,3,3,3,3,4,4,4,5,5,6};
__constant__ unsigned char c_pb[N_PAIRS] =
    {1,2,3,4,5,6,7,2,3,4,5,6,7,3,4,5,6,7,4,5,6,7,5,6,7,6,7,7};

// ---------------- helpers ----------------
__device__ __forceinline__ float ex2_approx(float x) {
    float y;
    asm("ex2.approx.ftz.f32 %0, %1;" : "=f"(y) : "f"(x));
    return y;
}
__device__ __forceinline__ unsigned long long pack2(float a, float b) {
    unsigned long long r;
    asm("mov.b64 %0, {%1, %2};" : "=l"(r) : "f"(a), "f"(b));
    return r;
}
__device__ __forceinline__ void unpack2(unsigned long long p, float& lo, float& hi) {
    asm("mov.b64 {%0, %1}, %2;" : "=f"(lo), "=f"(hi) : "l"(p));
}
__device__ __forceinline__ unsigned long long fma2(unsigned long long a,
                                                   unsigned long long b,
                                                   unsigned long long c) {
    unsigned long long d;
    asm("fma.rn.f32x2 %0, %1, %2, %3;" : "=l"(d) : "l"(a), "l"(b), "l"(c));
    return d;
}
__device__ __forceinline__ unsigned long long add2(unsigned long long a,
                                                   unsigned long long b) {
    unsigned long long d;
    asm("add.rn.f32x2 %0, %1, %2;" : "=l"(d) : "l"(a), "l"(b));
    return d;
}

// ---------------- kernel 1: fused pair compute ----------------
// 896 CTAs x 128 threads. CTA = (pair, iTile, jTile). Writes g_part[bid].
__global__ void __launch_bounds__(TPB) k_fused(const float* __restrict__ pos,
                                               const float* __restrict__ eul,
                                               const float* __restrict__ coord)
{
    __shared__ float sM[N_UNITS][12];                 // R(9) + pos(3) per unit
    __shared__ __align__(16) float svp[NJJ][4][2];    // packed j tile, 2KB
    __shared__ float ws[TPB / 32];

    int tid = threadIdx.x;
    int bid = blockIdx.x;

    int pairIdx = bid >> 5;          // 32 tiles per pair
    int rem     = bid & 31;
    int iTile   = rem >> 3;          // 0..3
    int jTile   = rem & 7;           // 0..7
    int a = c_pa[pairIdx];
    int b = c_pb[pairIdx];

    // ---- rotation matrices (8 lanes of warp 0) ----
    if (tid < N_UNITS) {
        int n = tid;
        float phi   = eul[3 * n + 0];
        float theta = eul[3 * n + 1];
        float psi   = eul[3 * n + 2];
        float sp, cp, st, ct, ss, cs;
        sincosf(phi,   &sp, &cp);
        sincosf(theta, &st, &ct);
        sincosf(psi,   &ss, &cs);
        sM[n][0] = cs * ct;
        sM[n][1] = cs * st * sp - ss * cp;
        sM[n][2] = cs * st * cp + ss * sp;
        sM[n][3] = ss * ct;
        sM[n][4] = ss * st * sp + cs * cp;
        sM[n][5] = ss * st * cp - cs * sp;
        sM[n][6] = -st;
        sM[n][7] = ct * sp;
        sM[n][8] = ct * cp;
        sM[n][9]  = pos[3 * n + 0];
        sM[n][10] = pos[3 * n + 1];
        sM[n][11] = pos[3 * n + 2];
    }
    __syncthreads();

    // ---- stage j tile (all 128 threads, one j-point each) ----
    float jsq;
    {
        int jm = jTile * JTILE + tid;
        float cx = coord[3 * jm + 0];
        float cy = coord[3 * jm + 1];
        float cz = coord[3 * jm + 2];
        float tx = fmaf(sM[b][0], cx, fmaf(sM[b][1], cy, fmaf(sM[b][2], cz, sM[b][9])));
        float ty = fmaf(sM[b][3], cx, fmaf(sM[b][4], cy, fmaf(sM[b][5], cz, sM[b][10])));
        float tz = fmaf(sM[b][6], cx, fmaf(sM[b][7], cy, fmaf(sM[b][8], cz, sM[b][11])));
        float sq = fmaf(tx, tx, fmaf(ty, ty, tz * tz));
        float h  = LOG2E * (0.5f - sq);
        int jj = tid >> 1, half = tid & 1;
        svp[jj][0][half] = tx;
        svp[jj][1][half] = ty;
        svp[jj][2][half] = tz;
        svp[jj][3][half] = h;
        jsq = sq;
    }

    // ---- transform own 2 i-points -> packed registers ----
    unsigned long long u0x, u0y, u0z, u0w, u1x, u1y, u1z, u1w;
    float isq;
    {
        int mi = iTile * ITILE + tid * I_PER_THREAD;
        float r0 = sM[a][0], r1 = sM[a][1], r2 = sM[a][2];
        float r3 = sM[a][3], r4 = sM[a][4], r5 = sM[a][5];
        float r6 = sM[a][6], r7 = sM[a][7], r8 = sM[a][8];
        float px = sM[a][9], py = sM[a][10], pz = sM[a][11];

        float cx0 = coord[3 * mi + 0], cy0 = coord[3 * mi + 1], cz0 = coord[3 * mi + 2];
        float cx1 = coord[3 * mi + 3], cy1 = coord[3 * mi + 4], cz1 = coord[3 * mi + 5];

        float tx0 = fmaf(r0, cx0, fmaf(r1, cy0, fmaf(r2, cz0, px)));
        float ty0 = fmaf(r3, cx0, fmaf(r4, cy0, fmaf(r5, cz0, py)));
        float tz0 = fmaf(r6, cx0, fmaf(r7, cy0, fmaf(r8, cz0, pz)));
        float tx1 = fmaf(r0, cx1, fmaf(r1, cy1, fmaf(r2, cz1, px)));
        float ty1 = fmaf(r3, cx1, fmaf(r4, cy1, fmaf(r5, cz1, py)));
        float tz1 = fmaf(r6, cx1, fmaf(r7, cy1, fmaf(r8, cz1, pz)));

        float sq0 = fmaf(tx0, tx0, fmaf(ty0, ty0, tz0 * tz0));
        float sq1 = fmaf(tx1, tx1, fmaf(ty1, ty1, tz1 * tz1));
        float h0  = LOG2E * (0.5f - sq0);
        float h1  = LOG2E * (0.5f - sq1);
        isq = sq0 + sq1;

        float s2 = 2.0f * LOG2E;
        u0x = pack2(s2 * tx0, s2 * tx0);
        u0y = pack2(s2 * ty0, s2 * ty0);
        u0z = pack2(s2 * tz0, s2 * tz0);
        u0w = pack2(h0, h0);
        u1x = pack2(s2 * tx1, s2 * tx1);
        u1y = pack2(s2 * ty1, s2 * ty1);
        u1z = pack2(s2 * tz1, s2 * tz1);
        u1w = pack2(h1, h1);
    }
    __syncthreads();

    // ---- main pair loop (proven structure; j from smem broadcast) ----
    float acc0 = 0.f, acc1 = 0.f, acc2 = 0.f, acc3 = 0.f;
    const ulonglong2* __restrict__ vp = (const ulonglong2*)&svp[0][0][0];

    #pragma unroll 4
    for (int q = 0; q < NJJ; q++) {
        ulonglong2 P0 = vp[2 * q + 0];   // {xx, yy}
        ulonglong2 P1 = vp[2 * q + 1];   // {zz, ww}

        unsigned long long s0 =
            fma2(u0x, P0.x, fma2(u0y, P0.y, fma2(u0z, P1.x, add2(u0w, P1.y))));
        unsigned long long s1 =
            fma2(u1x, P0.x, fma2(u1y, P0.y, fma2(u1z, P1.x, add2(u1w, P1.y))));

        float lo0, hi0, lo1, hi1;
        unpack2(s0, lo0, hi0);
        unpack2(s1, lo1, hi1);
        acc0 += ex2_approx(lo0);
        acc1 += ex2_approx(hi0);
        acc2 += ex2_approx(lo1);
        acc3 += ex2_approx(hi1);
    }

    // ---- fold per-thread extras, block-reduce, write partial ----
    float t = LAMBDA1 * ((acc0 + acc1) + (acc2 + acc3));
    // L1 i-side: units 0..6 owned by (b==a+1, jTile==0) CTAs
    if (b == a + 1 && jTile == 0) t += isq * (1.0f / (float)N_UNITS);
    // L1 unit 7: owned by pair (6,7), iTile==0, via j-points
    if (a == 6 && iTile == 0)     t += jsq * (1.0f / (float)N_UNITS);

    #pragma unroll
    for (int o = 16; o > 0; o >>= 1)
        t += __shfl_down_sync(0xFFFFFFFFu, t, o);

    int lane = tid & 31, wid = tid >> 5;
    if (lane == 0) ws[wid] = t;
    __syncthreads();

    if (tid == 0) {
        float s = 0.0f;
        #pragma unroll
        for (int w = 0; w < TPB / 32; w++) s += ws[w];
        g_part[bid] = s;
    }
}

// ---------------- kernel 2: finisher (1 CTA) ----------------
__global__ void __launch_bounds__(256) k_finish(const float* __restrict__ pos,
                                                float* __restrict__ out)
{
    int tid = threadIdx.x;
    float s = 0.0f;
    for (int i = tid; i < PAIR_CTAS; i += 256)
        s += g_part[i];

    #pragma unroll
    for (int o = 16; o > 0; o >>= 1)
        s += __shfl_down_sync(0xFFFFFFFFu, s, o);

    __shared__ float ws[8];
    int lane = tid & 31, wid = tid >> 5;
    if (lane == 0) ws[wid] = s;
    __syncthreads();

    if (tid == 0) {
        float tot = 0.0f;
        #pragma unroll
        for (int w = 0; w < 8; w++) tot += ws[w];
        float sx = 0.0f, sy = 0.0f, sz = 0.0f;
        #pragma unroll
        for (int k = 0; k < N_UNITS; k++) {
            sx += pos[3 * k + 0];
            sy += pos[3 * k + 1];
            sz += pos[3 * k + 2];
        }
        tot += ALPHA * (sx * sx + sy * sy + sz * sz);
        out[0] = tot;
    }
}

extern "C" void kernel_launch(void* const* d_in, const int* in_sizes, int n_in,
                              void* d_out, int out_size)
{
    const float* positions    = (const float*)d_in[0];
    const float* euler_angles = (const float*)d_in[1];
    const float* coordinates  = (const float*)d_in[2];
    float* out = (float*)d_out;
    (void)in_sizes; (void)n_in; (void)out_size;

    k_fused<<<PAIR_CTAS, TPB>>>(positions, euler_angles, coordinates);
    k_finish<<<1, 256>>>(positions, out);
}